// round 15
// baseline (speedup 1.0000x reference)
#include <cuda_runtime.h>
#include <cuda_bf16.h>
#include <math.h>
#include <stdint.h>

#define Nn 64
#define T  512
#define Dd 512
#define Hh 512
#define G4 2048   // 4*H
#define NB 128    // persistent blocks
#define BPG 32    // blocks per batch group

// ---------------- scratch (static device arrays) ----------------
__device__ __align__(128) float g_xW[(size_t)Nn * T * G4];          // [t][n][4H]
__device__ __align__(128) __nv_bfloat16 g_hh[2][Nn * Hh];           // h hi plane [n][k]
__device__ __align__(128) __nv_bfloat16 g_hl[2][Nn * Hh];           // h lo plane [n][k]
__device__ __align__(128) __nv_bfloat16 g_xh[(size_t)Nn * T * Dd];  // x hi [m][k]
__device__ __align__(128) __nv_bfloat16 g_xl[(size_t)Nn * T * Dd];  // x lo [m][k]
__device__ __align__(128) __nv_bfloat16 g_wxh[G4 * Dd];             // Wx^T hi [n][k]
__device__ __align__(128) __nv_bfloat16 g_wxl[G4 * Dd];             // Wx^T lo [n][k]
__device__ int g_gcnt[4];
__device__ int g_flag[4];

// ---------------- helpers ----------------
static __device__ __forceinline__ uint32_t s2u(const void* p) {
    return (uint32_t)__cvta_generic_to_shared(p);
}
static __device__ __forceinline__ void cpasync16(uint32_t dst, const void* src) {
    asm volatile("cp.async.cg.shared.global [%0], [%1], 16;" :: "r"(dst), "l"(src));
}
static __device__ __forceinline__ void ldsm4(uint32_t* r, uint32_t addr) {
    asm volatile("ldmatrix.sync.aligned.m8n8.x4.shared.b16 {%0,%1,%2,%3}, [%4];"
                 : "=r"(r[0]), "=r"(r[1]), "=r"(r[2]), "=r"(r[3]) : "r"(addr));
}
static __device__ __forceinline__ void mma16816(float* d, const uint32_t* a,
                                                uint32_t b0, uint32_t b1) {
    asm volatile("mma.sync.aligned.m16n8k16.row.col.f32.bf16.bf16.f32 "
                 "{%0,%1,%2,%3},{%4,%5,%6,%7},{%8,%9},{%0,%1,%2,%3};"
                 : "+f"(d[0]), "+f"(d[1]), "+f"(d[2]), "+f"(d[3])
                 : "r"(a[0]), "r"(a[1]), "r"(a[2]), "r"(a[3]), "r"(b0), "r"(b1));
}
// fast sigmoid / tanh (MUFU-based; tanh form saturates safely at both ends)
static __device__ __forceinline__ float fsigmoid(float x) {
    return __fdividef(1.f, 1.f + __expf(-x));
}
static __device__ __forceinline__ float ftanh(float x) {
    return __fdividef(2.f, 1.f + __expf(-2.f * x)) - 1.f;
}

// ---------------------------------------------------------------------------
// Merged prep: x -> bf16 hi/lo, Wx^T -> bf16 hi/lo, h0 -> planes, flags.
// ---------------------------------------------------------------------------
__global__ void prep(const float* __restrict__ x,
                     const float* __restrict__ Wx,
                     const float* __restrict__ h0) {
    int i = blockIdx.x * blockDim.x + threadIdx.x;
    if (i < Nn * T * Dd) {
        float v = x[i];
        __nv_bfloat16 hi = __float2bfloat16(v);
        g_xh[i] = hi;
        g_xl[i] = __float2bfloat16(v - __bfloat162float(hi));
    }
    if (i < G4 * Dd) {
        int n = i >> 9;
        int k = i & 511;
        float v = Wx[(size_t)k * G4 + n];
        __nv_bfloat16 hi = __float2bfloat16(v);
        g_wxh[i] = hi;
        g_wxl[i] = __float2bfloat16(v - __bfloat162float(hi));
    }
    if (i < Nn * Hh) {
        float v = h0[i];
        __nv_bfloat16 hi = __float2bfloat16(v);
        g_hh[0][i] = hi;
        g_hl[0][i] = __float2bfloat16(v - __bfloat162float(hi));
    }
    if (i < 4) { g_gcnt[i] = 0; g_flag[i] = 0; }
}

// ---------------------------------------------------------------------------
// GEMM 1 via HMMA bf16 3-term split (r14, best measured — unchanged).
// ---------------------------------------------------------------------------
#define GSTAGE 40960
#define GSMEM  (2 * GSTAGE)

__global__ __launch_bounds__(256) void gemm_xw_h(const float* __restrict__ b) {
    extern __shared__ char smem[];
    const uint32_t sbase = s2u(smem);

    const int tid  = threadIdx.x;
    const int lane = tid & 31;
    const int wid  = tid >> 5;
    const int wm   = wid >> 2;
    const int wn   = wid & 3;
    const int m0   = blockIdx.y * 128;
    const int n0   = blockIdx.x * 128;

    const int tile = lane >> 3;
    const int tr   = lane & 7;
    const uint32_t arow  = (tile & 1) * 8 + tr;
    const uint32_t akoff = (tile >> 1) * 16;
    const uint32_t brow  = (tile >> 1) * 8 + tr;
    const uint32_t bkoff = (tile & 1) * 16;

    float d[4][4][4];
#pragma unroll
    for (int i = 0; i < 4; i++)
#pragma unroll
        for (int j = 0; j < 4; j++)
#pragma unroll
            for (int l = 0; l < 4; l++) d[i][j][l] = 0.f;

#define G_ISSUE(S)                                                            \
    {                                                                         \
        const int buf = (S) & 1;                                              \
        _Pragma("unroll")                                                     \
        for (int it = 0; it < 8; it++) {                                      \
            int id  = it * 256 + tid;                                         \
            int op  = id >> 10;                                               \
            int pl  = (id >> 9) & 1;                                          \
            int row = (id & 511) >> 2;                                        \
            int p   = id & 3;                                                 \
            uint32_t dst = sbase + (uint32_t)(buf * GSTAGE + op * 20480 +     \
                                              pl * 10240 + row * 80 + p * 16);\
            const char* src;                                                  \
            if (op == 0)                                                      \
                src = (const char*)(pl ? g_xl : g_xh) +                       \
                      (size_t)(m0 + row) * 1024 + (S) * 64 + p * 16;          \
            else                                                              \
                src = (const char*)(pl ? g_wxl : g_wxh) +                     \
                      (size_t)(n0 + row) * 1024 + (S) * 64 + p * 16;          \
            cpasync16(dst, src);                                              \
        }                                                                     \
        asm volatile("cp.async.commit_group;");                               \
    }

    G_ISSUE(0)

    for (int s = 0; s < 16; s++) {
        if (s + 1 < 16) {
            G_ISSUE(s + 1)
            asm volatile("cp.async.wait_group 1;");
        } else {
            asm volatile("cp.async.wait_group 0;");
        }
        __syncthreads();

        const int buf = s & 1;
        const uint32_t ah_base = sbase + buf * GSTAGE +
                                 (wm * 64 + arow) * 80 + akoff;
        const uint32_t al_base = ah_base + 10240;
        const uint32_t bh_base = sbase + buf * GSTAGE + 20480 +
                                 (wn * 32 + brow) * 80 + bkoff;
        const uint32_t bl_base = bh_base + 10240;

#pragma unroll
        for (int kc = 0; kc < 2; kc++) {
            const uint32_t ko = kc * 32;
            uint32_t bh0[4], bh1[4], bl0[4], bl1[4];
            ldsm4(bh0, bh_base + ko);
            ldsm4(bh1, bh_base + 16 * 80 + ko);
            ldsm4(bl0, bl_base + ko);
            ldsm4(bl1, bl_base + 16 * 80 + ko);
#pragma unroll
            for (int mi = 0; mi < 4; mi++) {
                uint32_t ah[4], al[4];
                ldsm4(ah, ah_base + mi * 16 * 80 + ko);
                ldsm4(al, al_base + mi * 16 * 80 + ko);
                mma16816(d[mi][0], ah, bh0[0], bh0[1]);
                mma16816(d[mi][1], ah, bh0[2], bh0[3]);
                mma16816(d[mi][2], ah, bh1[0], bh1[1]);
                mma16816(d[mi][3], ah, bh1[2], bh1[3]);
                mma16816(d[mi][0], ah, bl0[0], bl0[1]);
                mma16816(d[mi][1], ah, bl0[2], bl0[3]);
                mma16816(d[mi][2], ah, bl1[0], bl1[1]);
                mma16816(d[mi][3], ah, bl1[2], bl1[3]);
                mma16816(d[mi][0], al, bh0[0], bh0[1]);
                mma16816(d[mi][1], al, bh0[2], bh0[3]);
                mma16816(d[mi][2], al, bh1[0], bh1[1]);
                mma16816(d[mi][3], al, bh1[2], bh1[3]);
            }
        }
        __syncthreads();
    }
#undef G_ISSUE

    const int cbase0 = n0 + wn * 32 + (lane & 3) * 2;
#pragma unroll
    for (int ni = 0; ni < 4; ni++) {
        const int cb = cbase0 + ni * 8;
        float2 bb = *(const float2*)&b[cb];
#pragma unroll
        for (int mi = 0; mi < 4; mi++) {
#pragma unroll
            for (int half = 0; half < 2; half++) {
                int m  = m0 + wm * 64 + mi * 16 + (lane >> 2) + half * 8;
                int tt = m & (T - 1);
                int nn = m >> 9;
                size_t row = ((size_t)tt * Nn + nn) * G4 + cb;
                *(float2*)&g_xW[row] =
                    make_float2(d[mi][ni][half * 2 + 0] + bb.x,
                                d[mi][ni][half * 2 + 1] + bb.y);
            }
        }
    }
}

// smem byte layout for scan (pitch 1040 B = 520 halves)
#define OFF_WHI  0
#define OFF_WLO  66560
#define OFF_HH   133120
#define OFF_HL   149760
#define OFF_SACC 166400
#define SMEM_BYTES (OFF_SACC + 4 * 64 * 20 * 4)

// ---------------------------------------------------------------------------
// Persistent HMMA scan (r13 structure; fast-math epilogue; barrier
// arrive/wait split with next-step xW prefetch between).
// ---------------------------------------------------------------------------
__global__ __launch_bounds__(256) void lstm_scan(const float* __restrict__ Wh,
                                                 float* __restrict__ out) {
    extern __shared__ char smem[];
    __nv_bfloat16* whi = (__nv_bfloat16*)(smem + OFF_WHI);
    __nv_bfloat16* wlo = (__nv_bfloat16*)(smem + OFF_WLO);
    float* sacc = (float*)(smem + OFF_SACC);   // [4][64][20]

    const int tid  = threadIdx.x;
    const int lane = tid & 31;
    const int wid  = tid >> 5;
    const int hb   = blockIdx.x;
    const int ng   = hb >> 5;
    const int hg   = hb & 31;
    const int mw   = wid & 1;
    const int kw   = wid >> 1;
    const int n_e  = tid & 15;
    const int u_e  = tid >> 4;

    for (int idx = tid; idx < 64 * 512; idx += 256) {
        int c = idx & 63;
        int k = idx >> 6;
        int u = c >> 2;
        int g = c & 3;
        float w = Wh[(size_t)k * G4 + g * Hh + hg * 16 + u];
        __nv_bfloat16 hi = __float2bfloat16(w);
        whi[c * 520 + k] = hi;
        wlo[c * 520 + k] = __float2bfloat16(w - __bfloat162float(hi));
    }

    const int tile = lane >> 3;
    const int tr   = lane & 7;
    const uint32_t a_row16 = (tile & 1) * 8 + tr;
    const uint32_t a_koff  = (tile >> 1) * 16;
    const uint32_t b_c     = (tile >> 1) * 8 + tr;
    const uint32_t b_koff  = (tile & 1) * 16;
    const uint32_t aHi0 = s2u(whi) + (mw * 32 + a_row16) * 1040 + a_koff;
    const uint32_t aHi1 = aHi0 + 16 * 1040;
    const uint32_t aLo0 = s2u(wlo) + (mw * 32 + a_row16) * 1040 + a_koff;
    const uint32_t aLo1 = aLo0 + 16 * 1040;
    const uint32_t bHH  = s2u(smem + OFF_HH) + b_c * 1040 + b_koff;
    const uint32_t bHL  = s2u(smem + OFF_HL) + b_c * 1040 + b_koff;

    const int gn = ng * 16 + n_e;
    const int gk = hg * 16 + u_e;

    float c_reg = 0.f;
    // prefetch xW slice for t = 0
    float xw0, xw1, xw2, xw3;
    {
        const float* xwp = g_xW + ((size_t)0 * Nn + gn) * G4 + hg * 16 + u_e;
        xw0 = xwp[0 * Hh]; xw1 = xwp[1 * Hh];
        xw2 = xwp[2 * Hh]; xw3 = xwp[3 * Hh];
    }

    for (int t = 0; t < T; t++) {
        const int cur = t & 1;
        const __nv_bfloat16* ghh = g_hh[cur];
        const __nv_bfloat16* ghl = g_hl[cur];

        // --- stage h planes: 4 chunks; chunk c = k16 units [c*16, c*16+16) ---
#pragma unroll
        for (int c = 0; c < 4; c++) {
#pragma unroll
            for (int it = 0; it < 2; it++) {
                int id = it * 256 + tid;
                int p  = id >> 8;
                int n  = (id >> 4) & 15;
                int q  = c * 16 + (id & 15);
                uint32_t dst = s2u(smem + (p ? OFF_HL : OFF_HH)) +
                               (uint32_t)n * 1040u + (uint32_t)q * 16u;
                const char* src = (const char*)(p ? ghl : ghh) +
                                  (size_t)(ng * 16 + n) * 1024 + (size_t)q * 16;
                cpasync16(dst, src);
            }
            asm volatile("cp.async.commit_group;");
        }

        float d00[4] = {0, 0, 0, 0}, d01[4] = {0, 0, 0, 0};
        float d10[4] = {0, 0, 0, 0}, d11[4] = {0, 0, 0, 0};

#define MMA_PHASE(C, WG)                                                      \
        {                                                                     \
            asm volatile("cp.async.wait_group %0;" :: "n"(WG));               \
            __syncthreads();                                                  \
            _Pragma("unroll")                                                 \
            for (int kc2 = 0; kc2 < 2; kc2++) {                               \
                const uint32_t off = (uint32_t)(((C) * 8 + kw * 2 + kc2) * 32); \
                uint32_t ah0[4], ah1[4], al0[4], al1[4], bh[4], bl[4];        \
                ldsm4(ah0, aHi0 + off);                                       \
                ldsm4(ah1, aHi1 + off);                                       \
                ldsm4(bh,  bHH  + off);                                       \
                ldsm4(bl,  bHL  + off);                                       \
                ldsm4(al0, aLo0 + off);                                       \
                ldsm4(al1, aLo1 + off);                                       \
                mma16816(d00, ah0, bh[0], bh[1]);                             \
                mma16816(d01, ah0, bh[2], bh[3]);                             \
                mma16816(d10, ah1, bh[0], bh[1]);                             \
                mma16816(d11, ah1, bh[2], bh[3]);                             \
                mma16816(d00, ah0, bl[0], bl[1]);                             \
                mma16816(d01, ah0, bl[2], bl[3]);                             \
                mma16816(d10, ah1, bl[0], bl[1]);                             \
                mma16816(d11, ah1, bl[2], bl[3]);                             \
                mma16816(d00, al0, bh[0], bh[1]);                             \
                mma16816(d01, al0, bh[2], bh[3]);                             \
                mma16816(d10, al1, bh[0], bh[1]);                             \
                mma16816(d11, al1, bh[2], bh[3]);                             \
            }                                                                 \
        }
        MMA_PHASE(0, 3)
        MMA_PHASE(1, 2)
        MMA_PHASE(2, 1)
        MMA_PHASE(3, 0)
#undef MMA_PHASE

        {
            const int crow = mw * 32 + (lane >> 2);
            const int ncol = (lane & 3) * 2;
            float* sa = sacc + kw * 64 * 20;
            *(float2*)&sa[(crow)      * 20 + ncol]     = make_float2(d00[0], d00[1]);
            *(float2*)&sa[(crow + 8)  * 20 + ncol]     = make_float2(d00[2], d00[3]);
            *(float2*)&sa[(crow)      * 20 + ncol + 8] = make_float2(d01[0], d01[1]);
            *(float2*)&sa[(crow + 8)  * 20 + ncol + 8] = make_float2(d01[2], d01[3]);
            *(float2*)&sa[(crow + 16) * 20 + ncol]     = make_float2(d10[0], d10[1]);
            *(float2*)&sa[(crow + 24) * 20 + ncol]     = make_float2(d10[2], d10[3]);
            *(float2*)&sa[(crow + 16) * 20 + ncol + 8] = make_float2(d11[0], d11[1]);
            *(float2*)&sa[(crow + 24) * 20 + ncol + 8] = make_float2(d11[2], d11[3]);
        }
        __syncthreads();

        // --- epilogue (fast-math transcendentals) ---
        {
            float ag[4];
#pragma unroll
            for (int g = 0; g < 4; g++) {
                int c = u_e * 4 + g;
                ag[g] = sacc[(0 * 64 + c) * 20 + n_e]
                      + sacc[(1 * 64 + c) * 20 + n_e]
                      + sacc[(2 * 64 + c) * 20 + n_e]
                      + sacc[(3 * 64 + c) * 20 + n_e];
            }
            ag[0] += xw0; ag[1] += xw1; ag[2] += xw2; ag[3] += xw3;

            float iv = fsigmoid(ag[0]);
            float fv = fsigmoid(ag[1]);
            float ov = fsigmoid(ag[2]);
            float gv = ftanh(ag[3]);

            c_reg = fv * c_reg + iv * gv;
            float hn = ov * ftanh(c_reg);

            __nv_bfloat16 hi = __float2bfloat16(hn);
            g_hh[cur ^ 1][gn * Hh + gk] = hi;
            g_hl[cur ^ 1][gn * Hh + gk] =
                __float2bfloat16(hn - __bfloat162float(hi));
            out[((size_t)gn * T + t) * Hh + gk] = hn;
        }
        __syncthreads();

        // --- barrier: arrive, prefetch next xW during the wait, then wait ---
        if (tid == 0) {
            __threadfence();
            int v = atomicAdd(&g_gcnt[ng], 1);
            if (v == BPG - 1) {
                g_gcnt[ng] = 0;
                __threadfence();
                *(volatile int*)&g_flag[ng] = t + 1;
            }
        }
        if (t + 1 < T) {
            const float* xwp = g_xW + ((size_t)(t + 1) * Nn + gn) * G4 +
                               hg * 16 + u_e;
            xw0 = xwp[0 * Hh]; xw1 = xwp[1 * Hh];
            xw2 = xwp[2 * Hh]; xw3 = xwp[3 * Hh];
        }
        if (tid == 0) {
            while (*(volatile int*)&g_flag[ng] < t + 1) { }
            __threadfence();
        }
        __syncthreads();
    }
}

// ---------------------------------------------------------------------------
// Launch
// ---------------------------------------------------------------------------
extern "C" void kernel_launch(void* const* d_in, const int* in_sizes, int n_in,
                              void* d_out, int out_size) {
    const float* x  = (const float*)d_in[0];
    const float* h0 = (const float*)d_in[1];
    const float* Wx = (const float*)d_in[2];
    const float* Wh = (const float*)d_in[3];
    const float* b  = (const float*)d_in[4];
    float* out = (float*)d_out;

    cudaFuncSetAttribute(lstm_scan, cudaFuncAttributeMaxDynamicSharedMemorySize,
                         SMEM_BYTES);
    cudaFuncSetAttribute(gemm_xw_h, cudaFuncAttributeMaxDynamicSharedMemorySize,
                         GSMEM);

    prep<<<((size_t)Nn * T * Dd + 255) / 256, 256>>>(x, Wx, h0);

    dim3 g1(G4 / 128, (Nn * T) / 128);   // (16, 256)
    gemm_xw_h<<<g1, 256, GSMEM>>>(b);

    lstm_scan<<<NB, 256, SMEM_BYTES>>>(Wh, out);
}

// round 16
// speedup vs baseline: 1.0566x; 1.0566x over previous
#include <cuda_runtime.h>
#include <cuda_bf16.h>
#include <math.h>
#include <stdint.h>

#define Nn 64
#define T  512
#define Dd 512
#define Hh 512
#define G4 2048   // 4*H
#define NB 128    // persistent blocks
#define BPG 32    // blocks per batch group

// ---------------- scratch (static device arrays) ----------------
__device__ __align__(128) float g_xW[(size_t)Nn * T * G4];          // [t][n][4H]
__device__ __align__(128) __nv_bfloat16 g_hh[2][Nn * Hh];           // h hi plane [n][k]
__device__ __align__(128) __nv_bfloat16 g_hl[2][Nn * Hh];           // h lo plane [n][k]
__device__ __align__(128) __nv_bfloat16 g_xh[(size_t)Nn * T * Dd];  // x hi [m][k]
__device__ __align__(128) __nv_bfloat16 g_xl[(size_t)Nn * T * Dd];  // x lo [m][k]
__device__ __align__(128) __nv_bfloat16 g_wxh[G4 * Dd];             // Wx^T hi [n][k]
__device__ __align__(128) __nv_bfloat16 g_wxl[G4 * Dd];             // Wx^T lo [n][k]
__device__ int g_gcnt[4];
__device__ int g_flag[4];

// ---------------- helpers ----------------
static __device__ __forceinline__ uint32_t s2u(const void* p) {
    return (uint32_t)__cvta_generic_to_shared(p);
}
static __device__ __forceinline__ void cpasync16(uint32_t dst, const void* src) {
    asm volatile("cp.async.cg.shared.global [%0], [%1], 16;" :: "r"(dst), "l"(src));
}
static __device__ __forceinline__ void ldsm4(uint32_t* r, uint32_t addr) {
    asm volatile("ldmatrix.sync.aligned.m8n8.x4.shared.b16 {%0,%1,%2,%3}, [%4];"
                 : "=r"(r[0]), "=r"(r[1]), "=r"(r[2]), "=r"(r[3]) : "r"(addr));
}
static __device__ __forceinline__ void mma16816(float* d, const uint32_t* a,
                                                uint32_t b0, uint32_t b1) {
    asm volatile("mma.sync.aligned.m16n8k16.row.col.f32.bf16.bf16.f32 "
                 "{%0,%1,%2,%3},{%4,%5,%6,%7},{%8,%9},{%0,%1,%2,%3};"
                 : "+f"(d[0]), "+f"(d[1]), "+f"(d[2]), "+f"(d[3])
                 : "r"(a[0]), "r"(a[1]), "r"(a[2]), "r"(a[3]), "r"(b0), "r"(b1));
}
static __device__ __forceinline__ float fsigmoid(float x) {
    return __fdividef(1.f, 1.f + __expf(-x));
}
static __device__ __forceinline__ float ftanh(float x) {
    return __fdividef(2.f, 1.f + __expf(-2.f * x)) - 1.f;
}

// ---------------------------------------------------------------------------
// Merged prep: x -> bf16 hi/lo, Wx^T -> bf16 hi/lo, h0 -> planes, flags.
// ---------------------------------------------------------------------------
__global__ void prep(const float* __restrict__ x,
                     const float* __restrict__ Wx,
                     const float* __restrict__ h0) {
    int i = blockIdx.x * blockDim.x + threadIdx.x;
    if (i < Nn * T * Dd) {
        float v = x[i];
        __nv_bfloat16 hi = __float2bfloat16(v);
        g_xh[i] = hi;
        g_xl[i] = __float2bfloat16(v - __bfloat162float(hi));
    }
    if (i < G4 * Dd) {
        int n = i >> 9;
        int k = i & 511;
        float v = Wx[(size_t)k * G4 + n];
        __nv_bfloat16 hi = __float2bfloat16(v);
        g_wxh[i] = hi;
        g_wxl[i] = __float2bfloat16(v - __bfloat162float(hi));
    }
    if (i < Nn * Hh) {
        float v = h0[i];
        __nv_bfloat16 hi = __float2bfloat16(v);
        g_hh[0][i] = hi;
        g_hl[0][i] = __float2bfloat16(v - __bfloat162float(hi));
    }
    if (i < 4) { g_gcnt[i] = 0; g_flag[i] = 0; }
}

// ---------------------------------------------------------------------------
// GEMM 1 via HMMA bf16 3-term split (r14, best measured — unchanged).
// ---------------------------------------------------------------------------
#define GSTAGE 40960
#define GSMEM  (2 * GSTAGE)

__global__ __launch_bounds__(256) void gemm_xw_h(const float* __restrict__ b) {
    extern __shared__ char smem[];
    const uint32_t sbase = s2u(smem);

    const int tid  = threadIdx.x;
    const int lane = tid & 31;
    const int wid  = tid >> 5;
    const int wm   = wid >> 2;
    const int wn   = wid & 3;
    const int m0   = blockIdx.y * 128;
    const int n0   = blockIdx.x * 128;

    const int tile = lane >> 3;
    const int tr   = lane & 7;
    const uint32_t arow  = (tile & 1) * 8 + tr;
    const uint32_t akoff = (tile >> 1) * 16;
    const uint32_t brow  = (tile >> 1) * 8 + tr;
    const uint32_t bkoff = (tile & 1) * 16;

    float d[4][4][4];
#pragma unroll
    for (int i = 0; i < 4; i++)
#pragma unroll
        for (int j = 0; j < 4; j++)
#pragma unroll
            for (int l = 0; l < 4; l++) d[i][j][l] = 0.f;

#define G_ISSUE(S)                                                            \
    {                                                                         \
        const int buf = (S) & 1;                                              \
        _Pragma("unroll")                                                     \
        for (int it = 0; it < 8; it++) {                                      \
            int id  = it * 256 + tid;                                         \
            int op  = id >> 10;                                               \
            int pl  = (id >> 9) & 1;                                          \
            int row = (id & 511) >> 2;                                        \
            int p   = id & 3;                                                 \
            uint32_t dst = sbase + (uint32_t)(buf * GSTAGE + op * 20480 +     \
                                              pl * 10240 + row * 80 + p * 16);\
            const char* src;                                                  \
            if (op == 0)                                                      \
                src = (const char*)(pl ? g_xl : g_xh) +                       \
                      (size_t)(m0 + row) * 1024 + (S) * 64 + p * 16;          \
            else                                                              \
                src = (const char*)(pl ? g_wxl : g_wxh) +                     \
                      (size_t)(n0 + row) * 1024 + (S) * 64 + p * 16;          \
            cpasync16(dst, src);                                              \
        }                                                                     \
        asm volatile("cp.async.commit_group;");                               \
    }

    G_ISSUE(0)

    for (int s = 0; s < 16; s++) {
        if (s + 1 < 16) {
            G_ISSUE(s + 1)
            asm volatile("cp.async.wait_group 1;");
        } else {
            asm volatile("cp.async.wait_group 0;");
        }
        __syncthreads();

        const int buf = s & 1;
        const uint32_t ah_base = sbase + buf * GSTAGE +
                                 (wm * 64 + arow) * 80 + akoff;
        const uint32_t al_base = ah_base + 10240;
        const uint32_t bh_base = sbase + buf * GSTAGE + 20480 +
                                 (wn * 32 + brow) * 80 + bkoff;
        const uint32_t bl_base = bh_base + 10240;

#pragma unroll
        for (int kc = 0; kc < 2; kc++) {
            const uint32_t ko = kc * 32;
            uint32_t bh0[4], bh1[4], bl0[4], bl1[4];
            ldsm4(bh0, bh_base + ko);
            ldsm4(bh1, bh_base + 16 * 80 + ko);
            ldsm4(bl0, bl_base + ko);
            ldsm4(bl1, bl_base + 16 * 80 + ko);
#pragma unroll
            for (int mi = 0; mi < 4; mi++) {
                uint32_t ah[4], al[4];
                ldsm4(ah, ah_base + mi * 16 * 80 + ko);
                ldsm4(al, al_base + mi * 16 * 80 + ko);
                mma16816(d[mi][0], ah, bh0[0], bh0[1]);
                mma16816(d[mi][1], ah, bh0[2], bh0[3]);
                mma16816(d[mi][2], ah, bh1[0], bh1[1]);
                mma16816(d[mi][3], ah, bh1[2], bh1[3]);
                mma16816(d[mi][0], ah, bl0[0], bl0[1]);
                mma16816(d[mi][1], ah, bl0[2], bl0[3]);
                mma16816(d[mi][2], ah, bl1[0], bl1[1]);
                mma16816(d[mi][3], ah, bl1[2], bl1[3]);
                mma16816(d[mi][0], al, bh0[0], bh0[1]);
                mma16816(d[mi][1], al, bh0[2], bh0[3]);
                mma16816(d[mi][2], al, bh1[0], bh1[1]);
                mma16816(d[mi][3], al, bh1[2], bh1[3]);
            }
        }
        __syncthreads();
    }
#undef G_ISSUE

    const int cbase0 = n0 + wn * 32 + (lane & 3) * 2;
#pragma unroll
    for (int ni = 0; ni < 4; ni++) {
        const int cb = cbase0 + ni * 8;
        float2 bb = *(const float2*)&b[cb];
#pragma unroll
        for (int mi = 0; mi < 4; mi++) {
#pragma unroll
            for (int half = 0; half < 2; half++) {
                int m  = m0 + wm * 64 + mi * 16 + (lane >> 2) + half * 8;
                int tt = m & (T - 1);
                int nn = m >> 9;
                size_t row = ((size_t)tt * Nn + nn) * G4 + cb;
                *(float2*)&g_xW[row] =
                    make_float2(d[mi][ni][half * 2 + 0] + bb.x,
                                d[mi][ni][half * 2 + 1] + bb.y);
            }
        }
    }
}

// smem byte layout for scan (pitch 1040 B = 520 halves)
#define OFF_WHI  0
#define OFF_WLO  66560
#define OFF_HH   133120
#define OFF_HL   149760
#define OFF_SACC 166400                       // [4][64][20] fp32 = 20480
#define OFF_HSTH (OFF_SACC + 20480)           // [16][16] bf16 = 512
#define OFF_HSTL (OFF_HSTH + 512)             // [16][16] bf16 = 512
#define OFF_OST  (OFF_HSTL + 512)             // [16][16] fp32 = 1024
#define SMEM_BYTES (OFF_OST + 1024)

// ---------------------------------------------------------------------------
// Persistent HMMA scan. r14 structure; epilogue stores restructured:
//   * h hi/lo planes staged in smem, then written 4B-coalesced (these are the
//     only stores that must precede the barrier release).
//   * out[] store moved after the barrier arrive — overlaps the flag wait.
// ---------------------------------------------------------------------------
__global__ __launch_bounds__(256) void lstm_scan(const float* __restrict__ Wh,
                                                 float* __restrict__ out) {
    extern __shared__ char smem[];
    __nv_bfloat16* whi = (__nv_bfloat16*)(smem + OFF_WHI);
    __nv_bfloat16* wlo = (__nv_bfloat16*)(smem + OFF_WLO);
    float* sacc = (float*)(smem + OFF_SACC);           // [4][64][20]
    __nv_bfloat16* hsth = (__nv_bfloat16*)(smem + OFF_HSTH);   // [16n][16u]
    __nv_bfloat16* hstl = (__nv_bfloat16*)(smem + OFF_HSTL);
    float* ost = (float*)(smem + OFF_OST);             // [16n][16u]

    const int tid  = threadIdx.x;
    const int lane = tid & 31;
    const int wid  = tid >> 5;
    const int hb   = blockIdx.x;
    const int ng   = hb >> 5;
    const int hg   = hb & 31;
    const int mw   = wid & 1;
    const int kw   = wid >> 1;
    const int n_e  = tid & 15;
    const int u_e  = tid >> 4;

    for (int idx = tid; idx < 64 * 512; idx += 256) {
        int c = idx & 63;
        int k = idx >> 6;
        int u = c >> 2;
        int g = c & 3;
        float w = Wh[(size_t)k * G4 + g * Hh + hg * 16 + u];
        __nv_bfloat16 hi = __float2bfloat16(w);
        whi[c * 520 + k] = hi;
        wlo[c * 520 + k] = __float2bfloat16(w - __bfloat162float(hi));
    }

    const int tile = lane >> 3;
    const int tr   = lane & 7;
    const uint32_t a_row16 = (tile & 1) * 8 + tr;
    const uint32_t a_koff  = (tile >> 1) * 16;
    const uint32_t b_c     = (tile >> 1) * 8 + tr;
    const uint32_t b_koff  = (tile & 1) * 16;
    const uint32_t aHi0 = s2u(whi) + (mw * 32 + a_row16) * 1040 + a_koff;
    const uint32_t aHi1 = aHi0 + 16 * 1040;
    const uint32_t aLo0 = s2u(wlo) + (mw * 32 + a_row16) * 1040 + a_koff;
    const uint32_t aLo1 = aLo0 + 16 * 1040;
    const uint32_t bHH  = s2u(smem + OFF_HH) + b_c * 1040 + b_koff;
    const uint32_t bHL  = s2u(smem + OFF_HL) + b_c * 1040 + b_koff;

    const int gn = ng * 16 + n_e;

    float c_reg = 0.f;

    for (int t = 0; t < T; t++) {
        const int cur = t & 1;
        const __nv_bfloat16* ghh = g_hh[cur];
        const __nv_bfloat16* ghl = g_hl[cur];

        // prefetch this step's xW gate slice
        const float* xwp = g_xW + ((size_t)t * Nn + gn) * G4 + hg * 16 + u_e;
        float xw0 = xwp[0 * Hh];
        float xw1 = xwp[1 * Hh];
        float xw2 = xwp[2 * Hh];
        float xw3 = xwp[3 * Hh];

        // --- stage h planes: 4 chunks; chunk c = k16 units [c*16, c*16+16) ---
#pragma unroll
        for (int c = 0; c < 4; c++) {
#pragma unroll
            for (int it = 0; it < 2; it++) {
                int id = it * 256 + tid;
                int p  = id >> 8;
                int n  = (id >> 4) & 15;
                int q  = c * 16 + (id & 15);
                uint32_t dst = s2u(smem + (p ? OFF_HL : OFF_HH)) +
                               (uint32_t)n * 1040u + (uint32_t)q * 16u;
                const char* src = (const char*)(p ? ghl : ghh) +
                                  (size_t)(ng * 16 + n) * 1024 + (size_t)q * 16;
                cpasync16(dst, src);
            }
            asm volatile("cp.async.commit_group;");
        }

        float d00[4] = {0, 0, 0, 0}, d01[4] = {0, 0, 0, 0};
        float d10[4] = {0, 0, 0, 0}, d11[4] = {0, 0, 0, 0};

#define MMA_PHASE(C, WG)                                                      \
        {                                                                     \
            asm volatile("cp.async.wait_group %0;" :: "n"(WG));               \
            __syncthreads();                                                  \
            _Pragma("unroll")                                                 \
            for (int kc2 = 0; kc2 < 2; kc2++) {                               \
                const uint32_t off = (uint32_t)(((C) * 8 + kw * 2 + kc2) * 32); \
                uint32_t ah0[4], ah1[4], al0[4], al1[4], bh[4], bl[4];        \
                ldsm4(ah0, aHi0 + off);                                       \
                ldsm4(ah1, aHi1 + off);                                       \
                ldsm4(bh,  bHH  + off);                                       \
                ldsm4(bl,  bHL  + off);                                       \
                ldsm4(al0, aLo0 + off);                                       \
                ldsm4(al1, aLo1 + off);                                       \
                mma16816(d00, ah0, bh[0], bh[1]);                             \
                mma16816(d01, ah0, bh[2], bh[3]);                             \
                mma16816(d10, ah1, bh[0], bh[1]);                             \
                mma16816(d11, ah1, bh[2], bh[3]);                             \
                mma16816(d00, ah0, bl[0], bl[1]);                             \
                mma16816(d01, ah0, bl[2], bl[3]);                             \
                mma16816(d10, ah1, bl[0], bl[1]);                             \
                mma16816(d11, ah1, bl[2], bl[3]);                             \
                mma16816(d00, al0, bh[0], bh[1]);                             \
                mma16816(d01, al0, bh[2], bh[3]);                             \
                mma16816(d10, al1, bh[0], bh[1]);                             \
                mma16816(d11, al1, bh[2], bh[3]);                             \
            }                                                                 \
        }
        MMA_PHASE(0, 3)
        MMA_PHASE(1, 2)
        MMA_PHASE(2, 1)
        MMA_PHASE(3, 0)
#undef MMA_PHASE

        {
            const int crow = mw * 32 + (lane >> 2);
            const int ncol = (lane & 3) * 2;
            float* sa = sacc + kw * 64 * 20;
            *(float2*)&sa[(crow)      * 20 + ncol]     = make_float2(d00[0], d00[1]);
            *(float2*)&sa[(crow + 8)  * 20 + ncol]     = make_float2(d00[2], d00[3]);
            *(float2*)&sa[(crow)      * 20 + ncol + 8] = make_float2(d01[0], d01[1]);
            *(float2*)&sa[(crow + 8)  * 20 + ncol + 8] = make_float2(d01[2], d01[3]);
            *(float2*)&sa[(crow + 16) * 20 + ncol]     = make_float2(d10[0], d10[1]);
            *(float2*)&sa[(crow + 24) * 20 + ncol]     = make_float2(d10[2], d10[3]);
            *(float2*)&sa[(crow + 16) * 20 + ncol + 8] = make_float2(d11[0], d11[1]);
            *(float2*)&sa[(crow + 24) * 20 + ncol + 8] = make_float2(d11[2], d11[3]);
        }
        __syncthreads();

        // --- epilogue: compute + stage to smem (no scattered global stores) ---
        {
            float ag[4];
#pragma unroll
            for (int g = 0; g < 4; g++) {
                int c = u_e * 4 + g;
                ag[g] = sacc[(0 * 64 + c) * 20 + n_e]
                      + sacc[(1 * 64 + c) * 20 + n_e]
                      + sacc[(2 * 64 + c) * 20 + n_e]
                      + sacc[(3 * 64 + c) * 20 + n_e];
            }
            ag[0] += xw0; ag[1] += xw1; ag[2] += xw2; ag[3] += xw3;

            float iv = fsigmoid(ag[0]);
            float fv = fsigmoid(ag[1]);
            float ov = fsigmoid(ag[2]);
            float gv = ftanh(ag[3]);

            c_reg = fv * c_reg + iv * gv;
            float hn = ov * ftanh(c_reg);

            __nv_bfloat16 hi = __float2bfloat16(hn);
            hsth[n_e * 16 + u_e] = hi;
            hstl[n_e * 16 + u_e] = __float2bfloat16(hn - __bfloat162float(hi));
            ost[n_e * 16 + u_e]  = hn;
        }
        __syncthreads();

        // --- coalesced h-plane writes (must precede the release) ---
        {
            int plane = tid >> 7;            // 0: hi, 1: lo
            int r2    = tid & 127;
            int row   = r2 >> 3;             // 0..15 local n
            int part  = r2 & 7;              // 4B unit within 32B row
            uint32_t v = ((const uint32_t*)(plane ? (const void*)hstl
                                                  : (const void*)hsth))[row * 8 + part];
            __nv_bfloat16* dst = plane ? g_hl[cur ^ 1] : g_hh[cur ^ 1];
            *(uint32_t*)&dst[(ng * 16 + row) * Hh + hg * 16 + part * 2] = v;
        }
        __syncthreads();

        // --- arrive; out[] store overlaps the wait; then wait ---
        if (tid == 0) {
            __threadfence();
            int v = atomicAdd(&g_gcnt[ng], 1);
            if (v == BPG - 1) {
                g_gcnt[ng] = 0;
                __threadfence();
                *(volatile int*)&g_flag[ng] = t + 1;
            }
        }
        {
            int row = tid >> 4;              // local n
            int col = tid & 15;              // local u
            out[((size_t)(ng * 16 + row) * T + t) * Hh + hg * 16 + col] =
                ost[row * 16 + col];
        }
        if (tid == 0) {
            while (*(volatile int*)&g_flag[ng] < t + 1) { }
            __threadfence();
        }
        __syncthreads();
    }
}

// ---------------------------------------------------------------------------
// Launch
// ---------------------------------------------------------------------------
extern "C" void kernel_launch(void* const* d_in, const int* in_sizes, int n_in,
                              void* d_out, int out_size) {
    const float* x  = (const float*)d_in[0];
    const float* h0 = (const float*)d_in[1];
    const float* Wx = (const float*)d_in[2];
    const float* Wh = (const float*)d_in[3];
    const float* b  = (const float*)d_in[4];
    float* out = (float*)d_out;

    cudaFuncSetAttribute(lstm_scan, cudaFuncAttributeMaxDynamicSharedMemorySize,
                         SMEM_BYTES);
    cudaFuncSetAttribute(gemm_xw_h, cudaFuncAttributeMaxDynamicSharedMemorySize,
                         GSMEM);

    prep<<<((size_t)Nn * T * Dd + 255) / 256, 256>>>(x, Wx, h0);

    dim3 g1(G4 / 128, (Nn * T) / 128);   // (16, 256)
    gemm_xw_h<<<g1, 256, GSMEM>>>(b);

    lstm_scan<<<NB, 256, SMEM_BYTES>>>(Wh, out);
}

// round 17
// speedup vs baseline: 1.1492x; 1.0876x over previous
#include <cuda_runtime.h>
#include <cuda_bf16.h>
#include <math.h>
#include <stdint.h>

#define Nn 64
#define T  512
#define Dd 512
#define Hh 512
#define G4 2048   // 4*H
#define NB 128    // persistent blocks
#define BPG 32    // blocks per batch group

// ---------------- scratch (static device arrays) ----------------
__device__ __align__(128) float g_xW[(size_t)Nn * T * G4];          // [t][n][4H]
__device__ __align__(128) __nv_bfloat16 g_hh[2][Nn * Hh];           // h hi plane [n][k]
__device__ __align__(128) __nv_bfloat16 g_hl[2][Nn * Hh];           // h lo plane [n][k]
__device__ __align__(128) __nv_bfloat16 g_xh[(size_t)Nn * T * Dd];  // x hi [m][k]
__device__ __align__(128) __nv_bfloat16 g_xl[(size_t)Nn * T * Dd];  // x lo [m][k]
__device__ __align__(128) __nv_bfloat16 g_wxh[G4 * Dd];             // Wx^T hi [n][k]
__device__ __align__(128) __nv_bfloat16 g_wxl[G4 * Dd];             // Wx^T lo [n][k]
__device__ int g_gcnt[4];
__device__ int g_flag[4];

// ---------------- helpers ----------------
static __device__ __forceinline__ uint32_t s2u(const void* p) {
    return (uint32_t)__cvta_generic_to_shared(p);
}
static __device__ __forceinline__ void cpasync16(uint32_t dst, const void* src) {
    asm volatile("cp.async.cg.shared.global [%0], [%1], 16;" :: "r"(dst), "l"(src));
}
static __device__ __forceinline__ void ldsm4(uint32_t* r, uint32_t addr) {
    asm volatile("ldmatrix.sync.aligned.m8n8.x4.shared.b16 {%0,%1,%2,%3}, [%4];"
                 : "=r"(r[0]), "=r"(r[1]), "=r"(r[2]), "=r"(r[3]) : "r"(addr));
}
static __device__ __forceinline__ void mma16816(float* d, const uint32_t* a,
                                                uint32_t b0, uint32_t b1) {
    asm volatile("mma.sync.aligned.m16n8k16.row.col.f32.bf16.bf16.f32 "
                 "{%0,%1,%2,%3},{%4,%5,%6,%7},{%8,%9},{%0,%1,%2,%3};"
                 : "+f"(d[0]), "+f"(d[1]), "+f"(d[2]), "+f"(d[3])
                 : "r"(a[0]), "r"(a[1]), "r"(a[2]), "r"(a[3]), "r"(b0), "r"(b1));
}
static __device__ __forceinline__ float fsigmoid(float x) {
    return __fdividef(1.f, 1.f + __expf(-x));
}
static __device__ __forceinline__ float ftanh(float x) {
    return __fdividef(2.f, 1.f + __expf(-2.f * x)) - 1.f;
}

// ---------------------------------------------------------------------------
// Merged prep: x -> bf16 hi/lo, Wx^T -> bf16 hi/lo, h0 -> planes, flags.
// ---------------------------------------------------------------------------
__global__ void prep(const float* __restrict__ x,
                     const float* __restrict__ Wx,
                     const float* __restrict__ h0) {
    int i = blockIdx.x * blockDim.x + threadIdx.x;
    if (i < Nn * T * Dd) {
        float v = x[i];
        __nv_bfloat16 hi = __float2bfloat16(v);
        g_xh[i] = hi;
        g_xl[i] = __float2bfloat16(v - __bfloat162float(hi));
    }
    if (i < G4 * Dd) {
        int n = i >> 9;
        int k = i & 511;
        float v = Wx[(size_t)k * G4 + n];
        __nv_bfloat16 hi = __float2bfloat16(v);
        g_wxh[i] = hi;
        g_wxl[i] = __float2bfloat16(v - __bfloat162float(hi));
    }
    if (i < Nn * Hh) {
        float v = h0[i];
        __nv_bfloat16 hi = __float2bfloat16(v);
        g_hh[0][i] = hi;
        g_hl[0][i] = __float2bfloat16(v - __bfloat162float(hi));
    }
    if (i < 4) { g_gcnt[i] = 0; g_flag[i] = 0; }
}

// ---------------------------------------------------------------------------
// GEMM 1 via HMMA bf16 3-term split (r14, best measured — unchanged).
// ---------------------------------------------------------------------------
#define GSTAGE 40960
#define GSMEM  (2 * GSTAGE)

__global__ __launch_bounds__(256) void gemm_xw_h(const float* __restrict__ b) {
    extern __shared__ char smem[];
    const uint32_t sbase = s2u(smem);

    const int tid  = threadIdx.x;
    const int lane = tid & 31;
    const int wid  = tid >> 5;
    const int wm   = wid >> 2;
    const int wn   = wid & 3;
    const int m0   = blockIdx.y * 128;
    const int n0   = blockIdx.x * 128;

    const int tile = lane >> 3;
    const int tr   = lane & 7;
    const uint32_t arow  = (tile & 1) * 8 + tr;
    const uint32_t akoff = (tile >> 1) * 16;
    const uint32_t brow  = (tile >> 1) * 8 + tr;
    const uint32_t bkoff = (tile & 1) * 16;

    float d[4][4][4];
#pragma unroll
    for (int i = 0; i < 4; i++)
#pragma unroll
        for (int j = 0; j < 4; j++)
#pragma unroll
            for (int l = 0; l < 4; l++) d[i][j][l] = 0.f;

#define G_ISSUE(S)                                                            \
    {                                                                         \
        const int buf = (S) & 1;                                              \
        _Pragma("unroll")                                                     \
        for (int it = 0; it < 8; it++) {                                      \
            int id  = it * 256 + tid;                                         \
            int op  = id >> 10;                                               \
            int pl  = (id >> 9) & 1;                                          \
            int row = (id & 511) >> 2;                                        \
            int p   = id & 3;                                                 \
            uint32_t dst = sbase + (uint32_t)(buf * GSTAGE + op * 20480 +     \
                                              pl * 10240 + row * 80 + p * 16);\
            const char* src;                                                  \
            if (op == 0)                                                      \
                src = (const char*)(pl ? g_xl : g_xh) +                       \
                      (size_t)(m0 + row) * 1024 + (S) * 64 + p * 16;          \
            else                                                              \
                src = (const char*)(pl ? g_wxl : g_wxh) +                     \
                      (size_t)(n0 + row) * 1024 + (S) * 64 + p * 16;          \
            cpasync16(dst, src);                                              \
        }                                                                     \
        asm volatile("cp.async.commit_group;");                               \
    }

    G_ISSUE(0)

    for (int s = 0; s < 16; s++) {
        if (s + 1 < 16) {
            G_ISSUE(s + 1)
            asm volatile("cp.async.wait_group 1;");
        } else {
            asm volatile("cp.async.wait_group 0;");
        }
        __syncthreads();

        const int buf = s & 1;
        const uint32_t ah_base = sbase + buf * GSTAGE +
                                 (wm * 64 + arow) * 80 + akoff;
        const uint32_t al_base = ah_base + 10240;
        const uint32_t bh_base = sbase + buf * GSTAGE + 20480 +
                                 (wn * 32 + brow) * 80 + bkoff;
        const uint32_t bl_base = bh_base + 10240;

#pragma unroll
        for (int kc = 0; kc < 2; kc++) {
            const uint32_t ko = kc * 32;
            uint32_t bh0[4], bh1[4], bl0[4], bl1[4];
            ldsm4(bh0, bh_base + ko);
            ldsm4(bh1, bh_base + 16 * 80 + ko);
            ldsm4(bl0, bl_base + ko);
            ldsm4(bl1, bl_base + 16 * 80 + ko);
#pragma unroll
            for (int mi = 0; mi < 4; mi++) {
                uint32_t ah[4], al[4];
                ldsm4(ah, ah_base + mi * 16 * 80 + ko);
                ldsm4(al, al_base + mi * 16 * 80 + ko);
                mma16816(d[mi][0], ah, bh0[0], bh0[1]);
                mma16816(d[mi][1], ah, bh0[2], bh0[3]);
                mma16816(d[mi][2], ah, bh1[0], bh1[1]);
                mma16816(d[mi][3], ah, bh1[2], bh1[3]);
                mma16816(d[mi][0], ah, bl0[0], bl0[1]);
                mma16816(d[mi][1], ah, bl0[2], bl0[3]);
                mma16816(d[mi][2], ah, bl1[0], bl1[1]);
                mma16816(d[mi][3], ah, bl1[2], bl1[3]);
                mma16816(d[mi][0], al, bh0[0], bh0[1]);
                mma16816(d[mi][1], al, bh0[2], bh0[3]);
                mma16816(d[mi][2], al, bh1[0], bh1[1]);
                mma16816(d[mi][3], al, bh1[2], bh1[3]);
            }
        }
        __syncthreads();
    }
#undef G_ISSUE

    const int cbase0 = n0 + wn * 32 + (lane & 3) * 2;
#pragma unroll
    for (int ni = 0; ni < 4; ni++) {
        const int cb = cbase0 + ni * 8;
        float2 bb = *(const float2*)&b[cb];
#pragma unroll
        for (int mi = 0; mi < 4; mi++) {
#pragma unroll
            for (int half = 0; half < 2; half++) {
                int m  = m0 + wm * 64 + mi * 16 + (lane >> 2) + half * 8;
                int tt = m & (T - 1);
                int nn = m >> 9;
                size_t row = ((size_t)tt * Nn + nn) * G4 + cb;
                *(float2*)&g_xW[row] =
                    make_float2(d[mi][ni][half * 2 + 0] + bb.x,
                                d[mi][ni][half * 2 + 1] + bb.y);
            }
        }
    }
}

// smem byte layout for scan (pitch 1040 B = 520 halves)
#define OFF_WHI  0
#define OFF_WLO  66560
#define OFF_HH   133120
#define OFF_HL   149760
#define OFF_SACC 166400                       // [4][64][20] fp32 = 20480
#define OFF_HSTH (OFF_SACC + 20480)           // [16][16] bf16 = 512
#define OFF_HSTL (OFF_HSTH + 512)             // [16][16] bf16 = 512
#define OFF_OST  (OFF_HSTL + 512)             // [16][16] fp32 = 1024
#define SMEM_BYTES (OFF_OST + 1024)

// ---------------------------------------------------------------------------
// Persistent HMMA scan. r16 structure +:
//   * A (W) fragments hoisted into 128 registers before the t-loop — W planes
//     are step-invariant; smem already caps occupancy at 1 block/SM so the
//     registers are free (launch_bounds(256,1)). Removes 32 of 48 ldsm/warp/step.
//   * staging reduced to 2 chunks of 16KB (2 phase syncs instead of 4).
// ---------------------------------------------------------------------------
__global__ __launch_bounds__(256, 1) void lstm_scan(const float* __restrict__ Wh,
                                                    float* __restrict__ out) {
    extern __shared__ char smem[];
    __nv_bfloat16* whi = (__nv_bfloat16*)(smem + OFF_WHI);
    __nv_bfloat16* wlo = (__nv_bfloat16*)(smem + OFF_WLO);
    float* sacc = (float*)(smem + OFF_SACC);           // [4][64][20]
    __nv_bfloat16* hsth = (__nv_bfloat16*)(smem + OFF_HSTH);   // [16n][16u]
    __nv_bfloat16* hstl = (__nv_bfloat16*)(smem + OFF_HSTL);
    float* ost = (float*)(smem + OFF_OST);             // [16n][16u]

    const int tid  = threadIdx.x;
    const int lane = tid & 31;
    const int wid  = tid >> 5;
    const int hb   = blockIdx.x;
    const int ng   = hb >> 5;
    const int hg   = hb & 31;
    const int mw   = wid & 1;
    const int kw   = wid >> 1;
    const int n_e  = tid & 15;
    const int u_e  = tid >> 4;

    for (int idx = tid; idx < 64 * 512; idx += 256) {
        int c = idx & 63;
        int k = idx >> 6;
        int u = c >> 2;
        int g = c & 3;
        float w = Wh[(size_t)k * G4 + g * Hh + hg * 16 + u];
        __nv_bfloat16 hi = __float2bfloat16(w);
        whi[c * 520 + k] = hi;
        wlo[c * 520 + k] = __float2bfloat16(w - __bfloat162float(hi));
    }
    __syncthreads();   // W planes ready for hoisted ldsm

    const int tile = lane >> 3;
    const int tr   = lane & 7;
    const uint32_t a_row16 = (tile & 1) * 8 + tr;
    const uint32_t a_koff  = (tile >> 1) * 16;
    const uint32_t b_c     = (tile >> 1) * 8 + tr;
    const uint32_t b_koff  = (tile & 1) * 16;
    const uint32_t aHi0 = s2u(whi) + (mw * 32 + a_row16) * 1040 + a_koff;
    const uint32_t aHi1 = aHi0 + 16 * 1040;
    const uint32_t aLo0 = s2u(wlo) + (mw * 32 + a_row16) * 1040 + a_koff;
    const uint32_t aLo1 = aLo0 + 16 * 1040;
    const uint32_t bHH  = s2u(smem + OFF_HH) + b_c * 1040 + b_koff;
    const uint32_t bHL  = s2u(smem + OFF_HL) + b_c * 1040 + b_koff;

    // --- hoist all step-invariant A fragments into registers ---
    // warp handles mma-k-chunks (C*16 + kw*4 + kc2), C in {0,1}, kc2 in 0..3;
    // local fragment index f = C*4 + kc2.
    uint32_t rAh0[8][4], rAh1[8][4], rAl0[8][4], rAl1[8][4];
#pragma unroll
    for (int C = 0; C < 2; C++)
#pragma unroll
        for (int kc2 = 0; kc2 < 4; kc2++) {
            const int f = C * 4 + kc2;
            const uint32_t off = (uint32_t)((C * 16 + kw * 4 + kc2) * 32);
            ldsm4(rAh0[f], aHi0 + off);
            ldsm4(rAh1[f], aHi1 + off);
            ldsm4(rAl0[f], aLo0 + off);
            ldsm4(rAl1[f], aLo1 + off);
        }

    const int gn = ng * 16 + n_e;

    float c_reg = 0.f;

    for (int t = 0; t < T; t++) {
        const int cur = t & 1;
        const __nv_bfloat16* ghh = g_hh[cur];
        const __nv_bfloat16* ghl = g_hl[cur];

        // prefetch this step's xW gate slice
        const float* xwp = g_xW + ((size_t)t * Nn + gn) * G4 + hg * 16 + u_e;
        float xw0 = xwp[0 * Hh];
        float xw1 = xwp[1 * Hh];
        float xw2 = xwp[2 * Hh];
        float xw3 = xwp[3 * Hh];

        // --- stage h planes: 2 chunks of 16KB; chunk c = k16 units [c*32,+32) ---
#pragma unroll
        for (int c = 0; c < 2; c++) {
#pragma unroll
            for (int it = 0; it < 4; it++) {
                int id = it * 256 + tid;          // 0..1023
                int p  = id >> 9;                 // plane
                int n  = (id >> 5) & 15;
                int q  = c * 32 + (id & 31);      // 16B unit
                uint32_t dst = s2u(smem + (p ? OFF_HL : OFF_HH)) +
                               (uint32_t)n * 1040u + (uint32_t)q * 16u;
                const char* src = (const char*)(p ? ghl : ghh) +
                                  (size_t)(ng * 16 + n) * 1024 + (size_t)q * 16;
                cpasync16(dst, src);
            }
            asm volatile("cp.async.commit_group;");
        }

        float d00[4] = {0, 0, 0, 0}, d01[4] = {0, 0, 0, 0};
        float d10[4] = {0, 0, 0, 0}, d11[4] = {0, 0, 0, 0};

#define MMA_PHASE(C, WG)                                                      \
        {                                                                     \
            asm volatile("cp.async.wait_group %0;" :: "n"(WG));               \
            __syncthreads();                                                  \
            _Pragma("unroll")                                                 \
            for (int kc2 = 0; kc2 < 4; kc2++) {                               \
                const int f = (C) * 4 + kc2;                                  \
                const uint32_t off = (uint32_t)(((C) * 16 + kw * 4 + kc2) * 32); \
                uint32_t bh[4], bl[4];                                        \
                ldsm4(bh, bHH + off);                                         \
                ldsm4(bl, bHL + off);                                         \
                mma16816(d00, rAh0[f], bh[0], bh[1]);                         \
                mma16816(d01, rAh0[f], bh[2], bh[3]);                         \
                mma16816(d10, rAh1[f], bh[0], bh[1]);                         \
                mma16816(d11, rAh1[f], bh[2], bh[3]);                         \
                mma16816(d00, rAh0[f], bl[0], bl[1]);                         \
                mma16816(d01, rAh0[f], bl[2], bl[3]);                         \
                mma16816(d10, rAh1[f], bl[0], bl[1]);                         \
                mma16816(d11, rAh1[f], bl[2], bl[3]);                         \
                mma16816(d00, rAl0[f], bh[0], bh[1]);                         \
                mma16816(d01, rAl0[f], bh[2], bh[3]);                         \
                mma16816(d10, rAl1[f], bh[0], bh[1]);                         \
                mma16816(d11, rAl1[f], bh[2], bh[3]);                         \
            }                                                                 \
        }
        MMA_PHASE(0, 1)
        MMA_PHASE(1, 0)
#undef MMA_PHASE

        {
            const int crow = mw * 32 + (lane >> 2);
            const int ncol = (lane & 3) * 2;
            float* sa = sacc + kw * 64 * 20;
            *(float2*)&sa[(crow)      * 20 + ncol]     = make_float2(d00[0], d00[1]);
            *(float2*)&sa[(crow + 8)  * 20 + ncol]     = make_float2(d00[2], d00[3]);
            *(float2*)&sa[(crow)      * 20 + ncol + 8] = make_float2(d01[0], d01[1]);
            *(float2*)&sa[(crow + 8)  * 20 + ncol + 8] = make_float2(d01[2], d01[3]);
            *(float2*)&sa[(crow + 16) * 20 + ncol]     = make_float2(d10[0], d10[1]);
            *(float2*)&sa[(crow + 24) * 20 + ncol]     = make_float2(d10[2], d10[3]);
            *(float2*)&sa[(crow + 16) * 20 + ncol + 8] = make_float2(d11[0], d11[1]);
            *(float2*)&sa[(crow + 24) * 20 + ncol + 8] = make_float2(d11[2], d11[3]);
        }
        __syncthreads();

        // --- epilogue: compute + stage to smem ---
        {
            float ag[4];
#pragma unroll
            for (int g = 0; g < 4; g++) {
                int c = u_e * 4 + g;
                ag[g] = sacc[(0 * 64 + c) * 20 + n_e]
                      + sacc[(1 * 64 + c) * 20 + n_e]
                      + sacc[(2 * 64 + c) * 20 + n_e]
                      + sacc[(3 * 64 + c) * 20 + n_e];
            }
            ag[0] += xw0; ag[1] += xw1; ag[2] += xw2; ag[3] += xw3;

            float iv = fsigmoid(ag[0]);
            float fv = fsigmoid(ag[1]);
            float ov = fsigmoid(ag[2]);
            float gv = ftanh(ag[3]);

            c_reg = fv * c_reg + iv * gv;
            float hn = ov * ftanh(c_reg);

            __nv_bfloat16 hi = __float2bfloat16(hn);
            hsth[n_e * 16 + u_e] = hi;
            hstl[n_e * 16 + u_e] = __float2bfloat16(hn - __bfloat162float(hi));
            ost[n_e * 16 + u_e]  = hn;
        }
        __syncthreads();

        // --- coalesced h-plane writes (must precede the release) ---
        {
            int plane = tid >> 7;
            int r2    = tid & 127;
            int row   = r2 >> 3;
            int part  = r2 & 7;
            uint32_t v = ((const uint32_t*)(plane ? (const void*)hstl
                                                  : (const void*)hsth))[row * 8 + part];
            __nv_bfloat16* dst = plane ? g_hl[cur ^ 1] : g_hh[cur ^ 1];
            *(uint32_t*)&dst[(ng * 16 + row) * Hh + hg * 16 + part * 2] = v;
        }
        __syncthreads();

        // --- arrive; out[] store overlaps the wait; then wait ---
        if (tid == 0) {
            __threadfence();
            int v = atomicAdd(&g_gcnt[ng], 1);
            if (v == BPG - 1) {
                g_gcnt[ng] = 0;
                __threadfence();
                *(volatile int*)&g_flag[ng] = t + 1;
            }
        }
        {
            int row = tid >> 4;
            int col = tid & 15;
            out[((size_t)(ng * 16 + row) * T + t) * Hh + hg * 16 + col] =
                ost[row * 16 + col];
        }
        if (tid == 0) {
            while (*(volatile int*)&g_flag[ng] < t + 1) { }
            __threadfence();
        }
        __syncthreads();
    }
}

// ---------------------------------------------------------------------------
// Launch
// ---------------------------------------------------------------------------
extern "C" void kernel_launch(void* const* d_in, const int* in_sizes, int n_in,
                              void* d_out, int out_size) {
    const float* x  = (const float*)d_in[0];
    const float* h0 = (const float*)d_in[1];
    const float* Wx = (const float*)d_in[2];
    const float* Wh = (const float*)d_in[3];
    const float* b  = (const float*)d_in[4];
    float* out = (float*)d_out;

    cudaFuncSetAttribute(lstm_scan, cudaFuncAttributeMaxDynamicSharedMemorySize,
                         SMEM_BYTES);
    cudaFuncSetAttribute(gemm_xw_h, cudaFuncAttributeMaxDynamicSharedMemorySize,
                         GSMEM);

    prep<<<((size_t)Nn * T * Dd + 255) / 256, 256>>>(x, Wx, h0);

    dim3 g1(G4 / 128, (Nn * T) / 128);   // (16, 256)
    gemm_xw_h<<<g1, 256, GSMEM>>>(b);

    lstm_scan<<<NB, 256, SMEM_BYTES>>>(Wh, out);
}